// round 16
// baseline (speedup 1.0000x reference)
#include <cuda_runtime.h>
#include <cuda_fp16.h>
#include <math.h>

#define NN 100000
#define NE 3200000
#define NB 256      // scan blocks
#define CHUNK 391   // ceil(NN/NB)
#define NBLK_NODE 391    // node blocks (256 thr)
#define NBLK_EDGE4 3125  // edge blocks, 4 edges/thread (1024 edges/block)

typedef unsigned long long ull;

// ---------------- device scratch (static, allocation-free) ----------------
__device__ int    g_deg[NN];        // zeroed by k_scan after use (self-cleaning)
__device__ int    g_off[NN + 1];
__device__ int    g_cur[NN];
__device__ int    g_bagg[NB];
__device__ int    g_bpre[NB];
__device__ int    g_bflag[NB];      // reset by k_build for next replay
__device__ float  g_dis[NN];
__device__ unsigned int g_esrc[NE]; // CSR payload: src row byte-offset (src << 6)
__device__ float  g_ni[NN * 32];
__device__ __half g_hh[NN * 32];    // dis-scaled features: ĥ = h * dis
__device__ float  g_agg[NN * 32];

__device__ __forceinline__ void ffma2(ull& d, ull a, ull b) {
    asm("fma.rn.f32x2 %0, %1, %2, %0;" : "+l"(d) : "l"(a), "l"(b));
}
__device__ __forceinline__ void fadd2(ull& d, ull a) {
    asm("add.rn.f32x2 %0, %0, %1;" : "+l"(d) : "l"(a));
}
__device__ __forceinline__ ull pack2(float x) {
    ull r; asm("mov.b64 %0, {%1, %1};" : "=l"(r) : "f"(x)); return r;
}
__device__ __forceinline__ ull packf2(float2 v) {
    ull r; asm("mov.b64 %0, {%1, %2};" : "=l"(r) : "f"(v.x), "f"(v.y)); return r;
}
__device__ __forceinline__ float2 unpk(ull v) {
    float2 r; asm("mov.b64 {%0, %1}, %2;" : "=f"(r.x), "=f"(r.y) : "l"(v)); return r;
}
__device__ __forceinline__ ull mul2(ull a, ull b) {
    ull r; asm("mul.rn.f32x2 %0, %1, %2;" : "=l"(r) : "l"(a), "l"(b)); return r;
}

// per-block dtype detect: int64 indices < 100000 have zero high words
__device__ __forceinline__ int detect_is64_block(const unsigned int* eiw, int t, int* s_is64) {
    if (t < 32) {
        int ok = (eiw[2 * t + 1] == 0u) && (eiw[2 * (t + 32) + 1] == 0u);
        unsigned m = __ballot_sync(0xffffffffu, ok);
        if (t == 0) *s_is64 = (m == 0xffffffffu) ? 1 : 0;
    }
    __syncthreads();
    return *s_is64;
}

// load 4 consecutive edge indices (src or dst stream) at element offset e
__device__ __forceinline__ int4 load_idx4(const void* ei, long long e, int is64) {
    if (is64) {
        longlong2 a = *(const longlong2*)((const long long*)ei + e);
        longlong2 b = *(const longlong2*)((const long long*)ei + e + 2);
        return make_int4((int)a.x, (int)a.y, (int)b.x, (int)b.y);
    }
    return *(const int4*)((const int*)ei + e);
}

// ---------------- launch 0: fused preproc MLP + degree count (4 edges/thread) ----------------
__global__ void k_pre_deg(const float* __restrict__ x, const void* __restrict__ ei,
                          const float* __restrict__ Wp, const float* __restrict__ bp,
                          const float* __restrict__ W1, const float* __restrict__ b1,
                          const float* __restrict__ W2, const float* __restrict__ b2) {
    int t = threadIdx.x;
    if (blockIdx.x >= NBLK_NODE) {
        __shared__ int s_is64;
        int is64 = detect_is64_block((const unsigned int*)ei, t, &s_is64);
        long long e = (long long)(blockIdx.x - NBLK_NODE) * 1024 + t * 4;
        int4 d = load_idx4(ei, (long long)NE + e, is64);
        if ((unsigned)d.x < NN) atomicAdd(&g_deg[d.x], 1);
        if ((unsigned)d.y < NN) atomicAdd(&g_deg[d.y], 1);
        if ((unsigned)d.z < NN) atomicAdd(&g_deg[d.z], 1);
        if ((unsigned)d.w < NN) atomicAdd(&g_deg[d.w], 1);
        return;
    }
    __shared__ float sWp[60], sbp[10], sW1[320], sb1[32], sW2[320], sb2[32];
    if (t < 60) sWp[t] = Wp[t];
    if (t < 10) sbp[t] = bp[t];
    for (int k = t; k < 320; k += 256) { sW1[k] = W1[k]; sW2[k] = W2[k]; }
    if (t < 32) { sb1[t] = b1[t]; sb2[t] = b2[t]; }
    __syncthreads();
    int i = blockIdx.x * 256 + t;
    if (i >= NN) return;

    float xi[6];
    #pragma unroll
    for (int f = 0; f < 6; f++) xi[f] = x[(size_t)i * 6 + f];

    float h0[10];
    #pragma unroll
    for (int c = 0; c < 10; c++) {
        float s = sbp[c];
        #pragma unroll
        for (int f = 0; f < 6; f++) s += xi[f] * sWp[f * 10 + c];
        h0[c] = 1.0f / (1.0f + expf(-s));
    }

    float ni[32], hh[32];
    #pragma unroll
    for (int c = 0; c < 32; c++) { ni[c] = sb1[c]; hh[c] = sb2[c]; }
    #pragma unroll
    for (int k = 0; k < 10; k++) {
        float v = h0[k];
        const float4* w1 = (const float4*)(sW1 + k * 32);
        const float4* w2 = (const float4*)(sW2 + k * 32);
        #pragma unroll
        for (int q = 0; q < 8; q++) {
            float4 a = w1[q], b = w2[q];
            ni[4*q+0] += v * a.x; ni[4*q+1] += v * a.y; ni[4*q+2] += v * a.z; ni[4*q+3] += v * a.w;
            hh[4*q+0] += v * b.x; hh[4*q+1] += v * b.y; hh[4*q+2] += v * b.z; hh[4*q+3] += v * b.w;
        }
    }
    float4*  np = (float4*)(g_ni + (size_t)i * 32);
    __half2* hp = (__half2*)(g_hh + (size_t)i * 32);
    #pragma unroll
    for (int q = 0; q < 8; q++)
        np[q] = make_float4(fmaxf(ni[4*q],0.f), fmaxf(ni[4*q+1],0.f), fmaxf(ni[4*q+2],0.f), fmaxf(ni[4*q+3],0.f));
    #pragma unroll
    for (int q = 0; q < 16; q++)
        hp[q] = __floats2half2_rn(fmaxf(hh[2*q],0.f), fmaxf(hh[2*q+1],0.f));  // unscaled; scan scales by dis
}

// ---------------- launch 1: decoupled-lookback scan + dis + ĥ scaling ----------------
__global__ void k_scan() {
    int b = blockIdx.x, t = threadIdx.x;
    int lane = t & 31, wid = t >> 5;
    int gi = b * CHUNK + t;
    int val = (t < CHUNK && gi < NN) ? g_deg[gi] : 0;

    int v = val;
    #pragma unroll
    for (int o = 1; o < 32; o <<= 1) {
        int n = __shfl_up_sync(0xffffffffu, v, o);
        if (lane >= o) v += n;
    }
    __shared__ int ws[16];
    __shared__ int s_excl;
    if (lane == 31) ws[wid] = v;
    __syncthreads();
    if (t < 16) {
        int s = ws[t];
        #pragma unroll
        for (int o = 1; o < 16; o <<= 1) {
            int n = __shfl_up_sync(0xffffu, s, o);
            if (t >= o) s += n;
        }
        ws[t] = s;
    }
    __syncthreads();
    int total = ws[15];

    if (t == 0) {
        g_bagg[b] = total;
        if (b == 0) g_bpre[0] = total;
        __threadfence();
        atomicExch(&g_bflag[b], (b == 0) ? 2 : 1);
        if (b == 0) s_excl = 0;
    }

    if (b > 0 && t < 32) {
        int excl = 0;
        int j = b - 1;
        while (true) {
            int idx = j - lane;
            int f;
            do {
                f = (idx >= 0) ? atomicAdd(&g_bflag[idx], 0) : 2;
            } while (__ballot_sync(0xffffffffu, idx < 0 || f >= 1) != 0xffffffffu);
            __threadfence();
            unsigned pref = __ballot_sync(0xffffffffu, idx < 0 || f == 2);
            int stop = pref ? (__ffs(pref) - 1) : 32;
            int contrib = 0;
            if (idx >= 0) {
                if (lane < stop)       contrib = g_bagg[idx];
                else if (lane == stop) contrib = g_bpre[idx];
            }
            #pragma unroll
            for (int o = 16; o; o >>= 1) contrib += __shfl_down_sync(0xffffffffu, contrib, o);
            contrib = __shfl_sync(0xffffffffu, contrib, 0);
            excl += contrib;
            if (stop < 32) break;
            j -= 32;
        }
        if (t == 0) {
            g_bpre[b] = excl + total;
            __threadfence();
            atomicExch(&g_bflag[b], 2);
            s_excl = excl;
        }
    }
    __syncthreads();

    int base = s_excl + (wid ? ws[wid - 1] : 0);
    int excl_t = base + v - val;
    if (t < CHUNK && gi < NN) {
        g_off[gi] = excl_t;
        g_cur[gi] = excl_t;
        float d = rsqrtf((float)(val + 1));
        g_dis[gi] = d;
        g_deg[gi] = 0;
        if (gi == NN - 1) g_off[NN] = excl_t + val;
        // scale first-layer h by dis: ĥ = h * dis (in place)
        __half2* hp = (__half2*)(g_hh + (size_t)gi * 32);
        #pragma unroll
        for (int q = 0; q < 16; q++) {
            float2 f = __half22float2(hp[q]);
            hp[q] = __floats2half2_rn(f.x * d, f.y * d);
        }
    }
}

// ---------------- launch 2: CSR scatter (4 edges/thread, pre-shifted payload) ----------------
__global__ void k_build(const void* __restrict__ ei) {
    __shared__ int s_is64;
    int t = threadIdx.x;
    int is64 = detect_is64_block((const unsigned int*)ei, t, &s_is64);
    if (blockIdx.x == 0 && t < NB) g_bflag[t] = 0;   // reset for next replay
    long long e = (long long)blockIdx.x * 1024 + t * 4;
    int4 s = load_idx4(ei, e, is64);
    int4 d = load_idx4(ei, (long long)NE + e, is64);
    if ((unsigned)s.x < NN && (unsigned)d.x < NN) {
        int p = atomicAdd(&g_cur[d.x], 1);
        g_esrc[p] = (unsigned)s.x << 6;
    }
    if ((unsigned)s.y < NN && (unsigned)d.y < NN) {
        int p = atomicAdd(&g_cur[d.y], 1);
        g_esrc[p] = (unsigned)s.y << 6;
    }
    if ((unsigned)s.z < NN && (unsigned)d.z < NN) {
        int p = atomicAdd(&g_cur[d.z], 1);
        g_esrc[p] = (unsigned)s.z << 6;
    }
    if ((unsigned)s.w < NN && (unsigned)d.w < NN) {
        int p = atomicAdd(&g_cur[d.w], 1);
        g_esrc[p] = (unsigned)s.w << 6;
    }
}

// ---------------- edge aggregation: warp per dst node (R14 proven shape, 512-thr blocks) ----------------
// lane layout: g = lane>>3 (edge within 4-edge slot), sub = lane&7 (channel quad)
// Main loop processes 8 edges (2 slots): gathered half2 pairs are pre-added in
// fp16 (one extra fp16 rounding, within error budget) halving convert/add work.
#define AGG_EDGE1(kk)                                                           \
    {                                                                            \
        unsigned off = g_esrc[(kk) + g];                                         \
        uint2 hv = __ldg((const uint2*)((const char*)g_hh + off) + sub);         \
        fadd2(a01, packf2(__half22float2(*(__half2*)&hv.x)));                    \
        fadd2(a23, packf2(__half22float2(*(__half2*)&hv.y)));                    \
    }

__global__ __launch_bounds__(512)
void k_agg() {
    int w    = (blockIdx.x * blockDim.x + threadIdx.x) >> 5;
    int lane = threadIdx.x & 31;
    if (w >= NN) return;
    int g = lane >> 3, sub = lane & 7;
    int beg = g_off[w], end = g_off[w + 1];
    float dw = g_dis[w];                 // hoisted: latency overlaps the loop

    ull a01 = 0, a23 = 0;   // +0.0f == identity for the values here (post-relu, finite)
    if (g == 0) {   // self term: + ĥ_w
        uint2 hv = __ldg((const uint2*)((const char*)g_hh + ((unsigned)w << 6)) + sub);
        fadd2(a01, packf2(__half22float2(*(__half2*)&hv.x)));
        fadd2(a23, packf2(__half22float2(*(__half2*)&hv.y)));
    }

    int k = beg;
    for (; k + 8 <= end; k += 8) {
        unsigned o1 = g_esrc[k + g];
        unsigned o2 = g_esrc[k + 4 + g];
        uint2 h1 = __ldg((const uint2*)((const char*)g_hh + o1) + sub);
        uint2 h2 = __ldg((const uint2*)((const char*)g_hh + o2) + sub);
        __half2 s01 = __hadd2(*(__half2*)&h1.x, *(__half2*)&h2.x);
        __half2 s23 = __hadd2(*(__half2*)&h1.y, *(__half2*)&h2.y);
        fadd2(a01, packf2(__half22float2(s01)));
        fadd2(a23, packf2(__half22float2(s23)));
    }
    if (k + 4 <= end) { AGG_EDGE1(k); k += 4; }
    if (k + g < end)  { AGG_EDGE1(k); }

    // reduce across 4 edge groups (xor 8, 16 preserve sub) — packed adds
    #pragma unroll
    for (int o = 8; o <= 16; o <<= 1) {
        fadd2(a01, __shfl_xor_sync(0xffffffffu, a01, o));
        fadd2(a23, __shfl_xor_sync(0xffffffffu, a23, o));
    }
    if (lane < 8) {
        ull dw2 = pack2(dw);
        ull r01 = mul2(a01, dw2), r23 = mul2(a23, dw2);
        float2 p01 = unpk(r01), p23 = unpk(r23);
        ((float4*)(g_agg + (size_t)w * 32))[lane] =
            make_float4(p01.x, p01.y, p23.x, p23.y);
    }
}

// ---------------- per-layer node kernel: packed f32x2 FMA (512-thr blocks) ----------------
template <bool FINAL>
__global__ __launch_bounds__(512)
void k_node(const float* __restrict__ Wg,  const float* __restrict__ bg,
            const float* __restrict__ Wd,  const float* __restrict__ bd,
            const float* __restrict__ Wf1, const float* __restrict__ bf1,
            const float* __restrict__ Wf2, const float* __restrict__ bf2,
            float* __restrict__ out) {
    __shared__ __align__(16) float sWg[1024], sbg[32], sWd[2048], sbd[32];
    __shared__ __align__(16) float sWf1[2048], sbf1[32], sWf2[64], sbf2[2];
    int t = threadIdx.x;
    for (int i = t; i < 1024; i += 512) sWg[i] = Wg[i];
    for (int i = t; i < 2048; i += 512) sWd[i] = Wd[i];
    if (t < 32) { sbg[t] = bg[t]; sbd[t] = bd[t]; }
    if (FINAL) {
        for (int i = t; i < 2048; i += 512) sWf1[i] = Wf1[i];
        if (t < 64) sWf2[t] = Wf2[t];
        if (t < 32) sbf1[t] = bf1[t];
        if (t < 2)  sbf2[t] = bf2[t];
    }
    __syncthreads();
    int i = blockIdx.x * blockDim.x + t;
    if (i >= NN) return;

    float ar[32];
    {
        const float4* ap = (const float4*)(g_agg + (size_t)i * 32);
        #pragma unroll
        for (int q = 0; q < 8; q++) {
            float4 v = ap[q];
            ar[4*q] = v.x; ar[4*q+1] = v.y; ar[4*q+2] = v.z; ar[4*q+3] = v.w;
        }
    }
    // a = relu(agg @ Wg + bg)  -- packed f32x2
    ull acc[16];
    #pragma unroll
    for (int j = 0; j < 16; j++) acc[j] = ((const ull*)sbg)[j];
    #pragma unroll
    for (int k = 0; k < 32; k++) {
        ull xp = pack2(ar[k]);
        const ulonglong2* w = (const ulonglong2*)(sWg + k * 32);
        #pragma unroll
        for (int j = 0; j < 8; j++) {
            ulonglong2 ww = w[j];
            ffma2(acc[2*j], ww.x, xp);
            ffma2(acc[2*j+1], ww.y, xp);
        }
    }
    float a[32];
    #pragma unroll
    for (int j = 0; j < 16; j++) {
        float2 p = unpk(acc[j]);
        a[2*j] = fmaxf(p.x, 0.f); a[2*j+1] = fmaxf(p.y, 0.f);
    }

    float nr[32];
    {
        const float4* np = (const float4*)(g_ni + (size_t)i * 32);
        #pragma unroll
        for (int q = 0; q < 8; q++) {
            float4 v = np[q];
            nr[4*q] = v.x; nr[4*q+1] = v.y; nr[4*q+2] = v.z; nr[4*q+3] = v.w;
        }
    }
    // t = relu([ni, a] @ Wd + bd)
    #pragma unroll
    for (int j = 0; j < 16; j++) acc[j] = ((const ull*)sbd)[j];
    #pragma unroll
    for (int k = 0; k < 32; k++) {
        ull xp = pack2(nr[k]);
        const ulonglong2* w = (const ulonglong2*)(sWd + k * 32);
        #pragma unroll
        for (int j = 0; j < 8; j++) {
            ulonglong2 ww = w[j];
            ffma2(acc[2*j], ww.x, xp);
            ffma2(acc[2*j+1], ww.y, xp);
        }
    }
    #pragma unroll
    for (int k = 0; k < 32; k++) {
        ull xp = pack2(a[k]);
        const ulonglong2* w = (const ulonglong2*)(sWd + (32 + k) * 32);
        #pragma unroll
        for (int j = 0; j < 8; j++) {
            ulonglong2 ww = w[j];
            ffma2(acc[2*j], ww.x, xp);
            ffma2(acc[2*j+1], ww.y, xp);
        }
    }
    float tt[32];
    #pragma unroll
    for (int j = 0; j < 16; j++) {
        float2 p = unpk(acc[j]);
        tt[2*j] = fmaxf(p.x, 0.f); tt[2*j+1] = fmaxf(p.y, 0.f);
    }

    if (!FINAL) {
        float di = g_dis[i];                      // store ĥ' = relu(...)·dis for next layer
        __half2* hp = (__half2*)(g_hh + (size_t)i * 32);
        #pragma unroll
        for (int q = 0; q < 16; q++)
            hp[q] = __floats2half2_rn(tt[2*q] * di, tt[2*q+1] * di);
    } else {
        // z = relu([ni, t] @ Wf1 + bf1); out = z @ Wf2 + bf2
        #pragma unroll
        for (int j = 0; j < 16; j++) acc[j] = ((const ull*)sbf1)[j];
        #pragma unroll
        for (int k = 0; k < 32; k++) {
            ull xp = pack2(nr[k]);
            const ulonglong2* w = (const ulonglong2*)(sWf1 + k * 32);
            #pragma unroll
            for (int j = 0; j < 8; j++) {
                ulonglong2 ww = w[j];
                ffma2(acc[2*j], ww.x, xp);
                ffma2(acc[2*j+1], ww.y, xp);
            }
        }
        #pragma unroll
        for (int k = 0; k < 32; k++) {
            ull xp = pack2(tt[k]);
            const ulonglong2* w = (const ulonglong2*)(sWf1 + (32 + k) * 32);
            #pragma unroll
            for (int j = 0; j < 8; j++) {
                ulonglong2 ww = w[j];
                ffma2(acc[2*j], ww.x, xp);
                ffma2(acc[2*j+1], ww.y, xp);
            }
        }
        float o0 = sbf2[0], o1 = sbf2[1];
        #pragma unroll
        for (int j = 0; j < 16; j++) {
            float2 p = unpk(acc[j]);
            float z0 = fmaxf(p.x, 0.f), z1 = fmaxf(p.y, 0.f);
            o0 += z0 * sWf2[2*(2*j) + 0] + z1 * sWf2[2*(2*j+1) + 0];
            o1 += z0 * sWf2[2*(2*j) + 1] + z1 * sWf2[2*(2*j+1) + 1];
        }
        ((float2*)out)[i] = make_float2(o0, o1);
    }
}

// ---------------- launch ----------------
extern "C" void kernel_launch(void* const* d_in, const int* in_sizes, int n_in,
                              void* d_out, int out_size) {
    const float* x  = (const float*)d_in[0];
    const void*  ei = d_in[1];
    const float* Wpre = (const float*)d_in[2];
    const float* bpre = (const float*)d_in[3];
    const float* Wfc1 = (const float*)d_in[4];
    const float* bfc1 = (const float*)d_in[5];
    const float* Wfc2 = (const float*)d_in[6];
    const float* bfc2 = (const float*)d_in[7];
    const float* Wgcn = (const float*)d_in[8];
    const float* bgcn = (const float*)d_in[9];
    const float* Wden = (const float*)d_in[10];
    const float* bden = (const float*)d_in[11];
    const float* Wf1  = (const float*)d_in[12];
    const float* bf1  = (const float*)d_in[13];
    const float* Wf2  = (const float*)d_in[14];
    const float* bf2  = (const float*)d_in[15];
    float* out = (float*)d_out;

    k_pre_deg<<<NBLK_NODE + NBLK_EDGE4, 256>>>(x, ei, Wpre, bpre, Wfc1, bfc1, Wfc2, bfc2); // 0
    k_scan<<<NB, 512>>>();                                                                  // 1 (+hscale)
    k_build<<<NBLK_EDGE4, 256>>>(ei);                                                       // 2 (+flag reset)

    int ab = (NN * 32 + 511) / 512;   // 6250 blocks, 512 thr
    int nb = (NN + 511) / 512;        // 196 blocks, 512 thr
    for (int l = 0; l < 6; l++) {
        k_agg<<<ab, 512>>>();                                                               // 3 <- ncu capture
        if (l < 5)
            k_node<false><<<nb, 512>>>(Wgcn, bgcn, Wden, bden, Wf1, bf1, Wf2, bf2, out);
        else
            k_node<true><<<nb, 512>>>(Wgcn, bgcn, Wden, bden, Wf1, bf1, Wf2, bf2, out);
    }
}

// round 17
// speedup vs baseline: 1.1523x; 1.1523x over previous
#include <cuda_runtime.h>
#include <cuda_fp16.h>
#include <math.h>

#define NN 100000
#define NE 3200000
#define NB 256      // scan blocks
#define CHUNK 391   // ceil(NN/NB)
#define NBLK_NODE 391    // node blocks (256 thr)
#define NBLK_EDGE4 3125  // edge blocks, 4 edges/thread (1024 edges/block)

typedef unsigned long long ull;

// ---------------- device scratch (static, allocation-free) ----------------
__device__ int    g_deg[NN];        // zeroed by k_scan after use (self-cleaning)
__device__ int    g_off[NN + 1];
__device__ int    g_cur[NN];
__device__ int    g_bagg[NB];
__device__ int    g_bpre[NB];
__device__ int    g_bflag[NB];      // reset by k_build for next replay
__device__ float  g_dis[NN];
__device__ unsigned int g_esrc[NE]; // CSR payload: src row byte-offset (src << 6)
__device__ float  g_ni[NN * 32];
__device__ __half g_hh[NN * 32];    // dis-scaled features: ĥ = h * dis
__device__ float  g_agg[NN * 32];

__device__ __forceinline__ void ffma2(ull& d, ull a, ull b) {
    asm("fma.rn.f32x2 %0, %1, %2, %0;" : "+l"(d) : "l"(a), "l"(b));
}
__device__ __forceinline__ void fadd2(ull& d, ull a) {
    asm("add.rn.f32x2 %0, %0, %1;" : "+l"(d) : "l"(a));
}
__device__ __forceinline__ ull pack2(float x) {
    ull r; asm("mov.b64 %0, {%1, %1};" : "=l"(r) : "f"(x)); return r;
}
__device__ __forceinline__ ull packf2(float2 v) {
    ull r; asm("mov.b64 %0, {%1, %2};" : "=l"(r) : "f"(v.x), "f"(v.y)); return r;
}
__device__ __forceinline__ float2 unpk(ull v) {
    float2 r; asm("mov.b64 {%0, %1}, %2;" : "=f"(r.x), "=f"(r.y) : "l"(v)); return r;
}
__device__ __forceinline__ ull mul2(ull a, ull b) {
    ull r; asm("mul.rn.f32x2 %0, %1, %2;" : "=l"(r) : "l"(a), "l"(b)); return r;
}

// per-block dtype detect: int64 indices < 100000 have zero high words
__device__ __forceinline__ int detect_is64_block(const unsigned int* eiw, int t, int* s_is64) {
    if (t < 32) {
        int ok = (eiw[2 * t + 1] == 0u) && (eiw[2 * (t + 32) + 1] == 0u);
        unsigned m = __ballot_sync(0xffffffffu, ok);
        if (t == 0) *s_is64 = (m == 0xffffffffu) ? 1 : 0;
    }
    __syncthreads();
    return *s_is64;
}

// load 4 consecutive edge indices (src or dst stream) at element offset e
__device__ __forceinline__ int4 load_idx4(const void* ei, long long e, int is64) {
    if (is64) {
        longlong2 a = *(const longlong2*)((const long long*)ei + e);
        longlong2 b = *(const longlong2*)((const long long*)ei + e + 2);
        return make_int4((int)a.x, (int)a.y, (int)b.x, (int)b.y);
    }
    return *(const int4*)((const int*)ei + e);
}

// ---------------- launch 0: fused preproc MLP + degree count (4 edges/thread) ----------------
__global__ void k_pre_deg(const float* __restrict__ x, const void* __restrict__ ei,
                          const float* __restrict__ Wp, const float* __restrict__ bp,
                          const float* __restrict__ W1, const float* __restrict__ b1,
                          const float* __restrict__ W2, const float* __restrict__ b2) {
    int t = threadIdx.x;
    if (blockIdx.x >= NBLK_NODE) {
        __shared__ int s_is64;
        int is64 = detect_is64_block((const unsigned int*)ei, t, &s_is64);
        long long e = (long long)(blockIdx.x - NBLK_NODE) * 1024 + t * 4;
        int4 d = load_idx4(ei, (long long)NE + e, is64);
        if ((unsigned)d.x < NN) atomicAdd(&g_deg[d.x], 1);
        if ((unsigned)d.y < NN) atomicAdd(&g_deg[d.y], 1);
        if ((unsigned)d.z < NN) atomicAdd(&g_deg[d.z], 1);
        if ((unsigned)d.w < NN) atomicAdd(&g_deg[d.w], 1);
        return;
    }
    __shared__ float sWp[60], sbp[10], sW1[320], sb1[32], sW2[320], sb2[32];
    if (t < 60) sWp[t] = Wp[t];
    if (t < 10) sbp[t] = bp[t];
    for (int k = t; k < 320; k += 256) { sW1[k] = W1[k]; sW2[k] = W2[k]; }
    if (t < 32) { sb1[t] = b1[t]; sb2[t] = b2[t]; }
    __syncthreads();
    int i = blockIdx.x * 256 + t;
    if (i >= NN) return;

    float xi[6];
    #pragma unroll
    for (int f = 0; f < 6; f++) xi[f] = x[(size_t)i * 6 + f];

    float h0[10];
    #pragma unroll
    for (int c = 0; c < 10; c++) {
        float s = sbp[c];
        #pragma unroll
        for (int f = 0; f < 6; f++) s += xi[f] * sWp[f * 10 + c];
        h0[c] = 1.0f / (1.0f + expf(-s));
    }

    float ni[32], hh[32];
    #pragma unroll
    for (int c = 0; c < 32; c++) { ni[c] = sb1[c]; hh[c] = sb2[c]; }
    #pragma unroll
    for (int k = 0; k < 10; k++) {
        float v = h0[k];
        const float4* w1 = (const float4*)(sW1 + k * 32);
        const float4* w2 = (const float4*)(sW2 + k * 32);
        #pragma unroll
        for (int q = 0; q < 8; q++) {
            float4 a = w1[q], b = w2[q];
            ni[4*q+0] += v * a.x; ni[4*q+1] += v * a.y; ni[4*q+2] += v * a.z; ni[4*q+3] += v * a.w;
            hh[4*q+0] += v * b.x; hh[4*q+1] += v * b.y; hh[4*q+2] += v * b.z; hh[4*q+3] += v * b.w;
        }
    }
    float4*  np = (float4*)(g_ni + (size_t)i * 32);
    __half2* hp = (__half2*)(g_hh + (size_t)i * 32);
    #pragma unroll
    for (int q = 0; q < 8; q++)
        np[q] = make_float4(fmaxf(ni[4*q],0.f), fmaxf(ni[4*q+1],0.f), fmaxf(ni[4*q+2],0.f), fmaxf(ni[4*q+3],0.f));
    #pragma unroll
    for (int q = 0; q < 16; q++)
        hp[q] = __floats2half2_rn(fmaxf(hh[2*q],0.f), fmaxf(hh[2*q+1],0.f));  // unscaled; scan scales by dis
}

// ---------------- launch 1: decoupled-lookback scan + dis + ĥ scaling ----------------
__global__ void k_scan() {
    int b = blockIdx.x, t = threadIdx.x;
    int lane = t & 31, wid = t >> 5;
    int gi = b * CHUNK + t;
    int val = (t < CHUNK && gi < NN) ? g_deg[gi] : 0;

    int v = val;
    #pragma unroll
    for (int o = 1; o < 32; o <<= 1) {
        int n = __shfl_up_sync(0xffffffffu, v, o);
        if (lane >= o) v += n;
    }
    __shared__ int ws[16];
    __shared__ int s_excl;
    if (lane == 31) ws[wid] = v;
    __syncthreads();
    if (t < 16) {
        int s = ws[t];
        #pragma unroll
        for (int o = 1; o < 16; o <<= 1) {
            int n = __shfl_up_sync(0xffffu, s, o);
            if (t >= o) s += n;
        }
        ws[t] = s;
    }
    __syncthreads();
    int total = ws[15];

    if (t == 0) {
        g_bagg[b] = total;
        if (b == 0) g_bpre[0] = total;
        __threadfence();
        atomicExch(&g_bflag[b], (b == 0) ? 2 : 1);
        if (b == 0) s_excl = 0;
    }

    if (b > 0 && t < 32) {
        int excl = 0;
        int j = b - 1;
        while (true) {
            int idx = j - lane;
            int f;
            do {
                f = (idx >= 0) ? atomicAdd(&g_bflag[idx], 0) : 2;
            } while (__ballot_sync(0xffffffffu, idx < 0 || f >= 1) != 0xffffffffu);
            __threadfence();
            unsigned pref = __ballot_sync(0xffffffffu, idx < 0 || f == 2);
            int stop = pref ? (__ffs(pref) - 1) : 32;
            int contrib = 0;
            if (idx >= 0) {
                if (lane < stop)       contrib = g_bagg[idx];
                else if (lane == stop) contrib = g_bpre[idx];
            }
            #pragma unroll
            for (int o = 16; o; o >>= 1) contrib += __shfl_down_sync(0xffffffffu, contrib, o);
            contrib = __shfl_sync(0xffffffffu, contrib, 0);
            excl += contrib;
            if (stop < 32) break;
            j -= 32;
        }
        if (t == 0) {
            g_bpre[b] = excl + total;
            __threadfence();
            atomicExch(&g_bflag[b], 2);
            s_excl = excl;
        }
    }
    __syncthreads();

    int base = s_excl + (wid ? ws[wid - 1] : 0);
    int excl_t = base + v - val;
    if (t < CHUNK && gi < NN) {
        g_off[gi] = excl_t;
        g_cur[gi] = excl_t;
        float d = rsqrtf((float)(val + 1));
        g_dis[gi] = d;
        g_deg[gi] = 0;
        if (gi == NN - 1) g_off[NN] = excl_t + val;
        // scale first-layer h by dis: ĥ = h * dis (in place)
        __half2* hp = (__half2*)(g_hh + (size_t)gi * 32);
        #pragma unroll
        for (int q = 0; q < 16; q++) {
            float2 f = __half22float2(hp[q]);
            hp[q] = __floats2half2_rn(f.x * d, f.y * d);
        }
    }
}

// ---------------- launch 2: CSR scatter (4 edges/thread, pre-shifted payload) ----------------
__global__ void k_build(const void* __restrict__ ei) {
    __shared__ int s_is64;
    int t = threadIdx.x;
    int is64 = detect_is64_block((const unsigned int*)ei, t, &s_is64);
    if (blockIdx.x == 0 && t < NB) g_bflag[t] = 0;   // reset for next replay
    long long e = (long long)blockIdx.x * 1024 + t * 4;
    int4 s = load_idx4(ei, e, is64);
    int4 d = load_idx4(ei, (long long)NE + e, is64);
    if ((unsigned)s.x < NN && (unsigned)d.x < NN) {
        int p = atomicAdd(&g_cur[d.x], 1);
        g_esrc[p] = (unsigned)s.x << 6;
    }
    if ((unsigned)s.y < NN && (unsigned)d.y < NN) {
        int p = atomicAdd(&g_cur[d.y], 1);
        g_esrc[p] = (unsigned)s.y << 6;
    }
    if ((unsigned)s.z < NN && (unsigned)d.z < NN) {
        int p = atomicAdd(&g_cur[d.z], 1);
        g_esrc[p] = (unsigned)s.z << 6;
    }
    if ((unsigned)s.w < NN && (unsigned)d.w < NN) {
        int p = atomicAdd(&g_cur[d.w], 1);
        g_esrc[p] = (unsigned)s.w << 6;
    }
}

// ---------------- edge aggregation: warp per dst node (R14 proven shape) ----------------
// lane layout: g = lane>>3 (edge within 4-edge slot), sub = lane&7 (channel quad)
#define AGG_EDGE1(kk)                                                           \
    {                                                                            \
        unsigned off = g_esrc[(kk) + g];                                         \
        uint2 hv = __ldg((const uint2*)((const char*)g_hh + off) + sub);         \
        fadd2(a01, packf2(__half22float2(*(__half2*)&hv.x)));                    \
        fadd2(a23, packf2(__half22float2(*(__half2*)&hv.y)));                    \
    }

__global__ void k_agg() {
    int w    = (blockIdx.x * blockDim.x + threadIdx.x) >> 5;
    int lane = threadIdx.x & 31;
    if (w >= NN) return;
    int g = lane >> 3, sub = lane & 7;
    int beg = g_off[w], end = g_off[w + 1];

    ull a01 = 0, a23 = 0;   // +0.0f == identity for the values here (post-relu, finite)
    if (g == 0) {   // self term: + ĥ_w
        uint2 hv = __ldg((const uint2*)((const char*)g_hh + ((unsigned)w << 6)) + sub);
        fadd2(a01, packf2(__half22float2(*(__half2*)&hv.x)));
        fadd2(a23, packf2(__half22float2(*(__half2*)&hv.y)));
    }

    int k = beg;
    for (; k + 8 <= end; k += 8) {
        unsigned o1 = g_esrc[k + g];
        unsigned o2 = g_esrc[k + 4 + g];
        uint2 h1 = __ldg((const uint2*)((const char*)g_hh + o1) + sub);
        uint2 h2 = __ldg((const uint2*)((const char*)g_hh + o2) + sub);
        __half2 s01 = __hadd2(*(__half2*)&h1.x, *(__half2*)&h2.x);
        __half2 s23 = __hadd2(*(__half2*)&h1.y, *(__half2*)&h2.y);
        fadd2(a01, packf2(__half22float2(s01)));
        fadd2(a23, packf2(__half22float2(s23)));
    }
    if (k + 4 <= end) { AGG_EDGE1(k); k += 4; }
    if (k + g < end)  { AGG_EDGE1(k); }

    // reduce across 4 edge groups (xor 8, 16 preserve sub) — packed adds
    #pragma unroll
    for (int o = 8; o <= 16; o <<= 1) {
        fadd2(a01, __shfl_xor_sync(0xffffffffu, a01, o));
        fadd2(a23, __shfl_xor_sync(0xffffffffu, a23, o));
    }
    if (lane < 8) {
        ull dw2 = pack2(g_dis[w]);
        ull r01 = mul2(a01, dw2), r23 = mul2(a23, dw2);
        float2 p01 = unpk(r01), p23 = unpk(r23);
        ((float4*)(g_agg + (size_t)w * 32))[lane] =
            make_float4(p01.x, p01.y, p23.x, p23.y);
    }
}

// ---------------- per-layer node kernel: packed f32x2 FMA + PDL ----------------
// Launched with programmatic stream serialization: weight staging overlaps the
// tail of the preceding k_agg; cudaGridDependencySynchronize() guards g_agg reads.
template <bool FINAL>
__global__ void k_node(const float* __restrict__ Wg,  const float* __restrict__ bg,
                       const float* __restrict__ Wd,  const float* __restrict__ bd,
                       const float* __restrict__ Wf1, const float* __restrict__ bf1,
                       const float* __restrict__ Wf2, const float* __restrict__ bf2,
                       float* __restrict__ out) {
    __shared__ __align__(16) float sWg[1024], sbg[32], sWd[2048], sbd[32];
    __shared__ __align__(16) float sWf1[2048], sbf1[32], sWf2[64], sbf2[2];
    int t = threadIdx.x;
    // prelude: weight staging (independent of producer kernel's output)
    for (int i = t; i < 1024; i += 256) sWg[i] = Wg[i];
    for (int i = t; i < 2048; i += 256) sWd[i] = Wd[i];
    if (t < 32) { sbg[t] = bg[t]; sbd[t] = bd[t]; }
    if (FINAL) {
        for (int i = t; i < 2048; i += 256) sWf1[i] = Wf1[i];
        if (t < 64) sWf2[t] = Wf2[t];
        if (t < 32) sbf1[t] = bf1[t];
        if (t < 2)  sbf2[t] = bf2[t];
    }
    // wait for producer (k_agg) completion before touching g_agg / g_dis / g_hh
    cudaGridDependencySynchronize();
    __syncthreads();
    int i = blockIdx.x * blockDim.x + t;
    if (i >= NN) return;

    float ar[32];
    {
        const float4* ap = (const float4*)(g_agg + (size_t)i * 32);
        #pragma unroll
        for (int q = 0; q < 8; q++) {
            float4 v = ap[q];
            ar[4*q] = v.x; ar[4*q+1] = v.y; ar[4*q+2] = v.z; ar[4*q+3] = v.w;
        }
    }
    // a = relu(agg @ Wg + bg)  -- packed f32x2
    ull acc[16];
    #pragma unroll
    for (int j = 0; j < 16; j++) acc[j] = ((const ull*)sbg)[j];
    #pragma unroll
    for (int k = 0; k < 32; k++) {
        ull xp = pack2(ar[k]);
        const ulonglong2* w = (const ulonglong2*)(sWg + k * 32);
        #pragma unroll
        for (int j = 0; j < 8; j++) {
            ulonglong2 ww = w[j];
            ffma2(acc[2*j], ww.x, xp);
            ffma2(acc[2*j+1], ww.y, xp);
        }
    }
    float a[32];
    #pragma unroll
    for (int j = 0; j < 16; j++) {
        float2 p = unpk(acc[j]);
        a[2*j] = fmaxf(p.x, 0.f); a[2*j+1] = fmaxf(p.y, 0.f);
    }

    float nr[32];
    {
        const float4* np = (const float4*)(g_ni + (size_t)i * 32);
        #pragma unroll
        for (int q = 0; q < 8; q++) {
            float4 v = np[q];
            nr[4*q] = v.x; nr[4*q+1] = v.y; nr[4*q+2] = v.z; nr[4*q+3] = v.w;
        }
    }
    // t = relu([ni, a] @ Wd + bd)
    #pragma unroll
    for (int j = 0; j < 16; j++) acc[j] = ((const ull*)sbd)[j];
    #pragma unroll
    for (int k = 0; k < 32; k++) {
        ull xp = pack2(nr[k]);
        const ulonglong2* w = (const ulonglong2*)(sWd + k * 32);
        #pragma unroll
        for (int j = 0; j < 8; j++) {
            ulonglong2 ww = w[j];
            ffma2(acc[2*j], ww.x, xp);
            ffma2(acc[2*j+1], ww.y, xp);
        }
    }
    #pragma unroll
    for (int k = 0; k < 32; k++) {
        ull xp = pack2(a[k]);
        const ulonglong2* w = (const ulonglong2*)(sWd + (32 + k) * 32);
        #pragma unroll
        for (int j = 0; j < 8; j++) {
            ulonglong2 ww = w[j];
            ffma2(acc[2*j], ww.x, xp);
            ffma2(acc[2*j+1], ww.y, xp);
        }
    }
    float tt[32];
    #pragma unroll
    for (int j = 0; j < 16; j++) {
        float2 p = unpk(acc[j]);
        tt[2*j] = fmaxf(p.x, 0.f); tt[2*j+1] = fmaxf(p.y, 0.f);
    }

    if (!FINAL) {
        float di = g_dis[i];                      // store ĥ' = relu(...)·dis for next layer
        __half2* hp = (__half2*)(g_hh + (size_t)i * 32);
        #pragma unroll
        for (int q = 0; q < 16; q++)
            hp[q] = __floats2half2_rn(tt[2*q] * di, tt[2*q+1] * di);
    } else {
        // z = relu([ni, t] @ Wf1 + bf1); out = z @ Wf2 + bf2
        #pragma unroll
        for (int j = 0; j < 16; j++) acc[j] = ((const ull*)sbf1)[j];
        #pragma unroll
        for (int k = 0; k < 32; k++) {
            ull xp = pack2(nr[k]);
            const ulonglong2* w = (const ulonglong2*)(sWf1 + k * 32);
            #pragma unroll
            for (int j = 0; j < 8; j++) {
                ulonglong2 ww = w[j];
                ffma2(acc[2*j], ww.x, xp);
                ffma2(acc[2*j+1], ww.y, xp);
            }
        }
        #pragma unroll
        for (int k = 0; k < 32; k++) {
            ull xp = pack2(tt[k]);
            const ulonglong2* w = (const ulonglong2*)(sWf1 + (32 + k) * 32);
            #pragma unroll
            for (int j = 0; j < 8; j++) {
                ulonglong2 ww = w[j];
                ffma2(acc[2*j], ww.x, xp);
                ffma2(acc[2*j+1], ww.y, xp);
            }
        }
        float o0 = sbf2[0], o1 = sbf2[1];
        #pragma unroll
        for (int j = 0; j < 16; j++) {
            float2 p = unpk(acc[j]);
            float z0 = fmaxf(p.x, 0.f), z1 = fmaxf(p.y, 0.f);
            o0 += z0 * sWf2[2*(2*j) + 0] + z1 * sWf2[2*(2*j+1) + 0];
            o1 += z0 * sWf2[2*(2*j) + 1] + z1 * sWf2[2*(2*j+1) + 1];
        }
        ((float2*)out)[i] = make_float2(o0, o1);
    }
}

// ---------------- launch ----------------
extern "C" void kernel_launch(void* const* d_in, const int* in_sizes, int n_in,
                              void* d_out, int out_size) {
    const float* x  = (const float*)d_in[0];
    const void*  ei = d_in[1];
    const float* Wpre = (const float*)d_in[2];
    const float* bpre = (const float*)d_in[3];
    const float* Wfc1 = (const float*)d_in[4];
    const float* bfc1 = (const float*)d_in[5];
    const float* Wfc2 = (const float*)d_in[6];
    const float* bfc2 = (const float*)d_in[7];
    const float* Wgcn = (const float*)d_in[8];
    const float* bgcn = (const float*)d_in[9];
    const float* Wden = (const float*)d_in[10];
    const float* bden = (const float*)d_in[11];
    const float* Wf1  = (const float*)d_in[12];
    const float* bf1  = (const float*)d_in[13];
    const float* Wf2  = (const float*)d_in[14];
    const float* bf2  = (const float*)d_in[15];
    float* out = (float*)d_out;

    k_pre_deg<<<NBLK_NODE + NBLK_EDGE4, 256>>>(x, ei, Wpre, bpre, Wfc1, bfc1, Wfc2, bfc2); // 0
    k_scan<<<NB, 512>>>();                                                                  // 1 (+hscale)
    k_build<<<NBLK_EDGE4, 256>>>(ei);                                                       // 2 (+flag reset)

    int ab = (NN * 32 + 255) / 256;   // 12500 blocks, 256 thr
    int nb = (NN + 255) / 256;        // 391 blocks, 256 thr

    // PDL launch config for k_node: overlap weight staging with k_agg tail
    cudaLaunchAttribute pdlAttr[1];
    pdlAttr[0].id = cudaLaunchAttributeProgrammaticStreamSerialization;
    pdlAttr[0].val.programmaticStreamSerializationAllowed = 1;
    cudaLaunchConfig_t cfg = {};
    cfg.gridDim  = dim3((unsigned)nb, 1, 1);
    cfg.blockDim = dim3(256, 1, 1);
    cfg.dynamicSmemBytes = 0;
    cfg.stream = 0;
    cfg.attrs = pdlAttr;
    cfg.numAttrs = 1;

    for (int l = 0; l < 6; l++) {
        k_agg<<<ab, 256>>>();                                                               // 3 <- ncu capture
        if (l < 5)
            cudaLaunchKernelEx(&cfg, k_node<false>, Wgcn, bgcn, Wden, bden, Wf1, bf1, Wf2, bf2, out);
        else
            cudaLaunchKernelEx(&cfg, k_node<true>,  Wgcn, bgcn, Wden, bden, Wf1, bf1, Wf2, bf2, out);
    }
}